// round 9
// baseline (speedup 1.0000x reference)
#include <cuda_runtime.h>
#include <cuda_bf16.h>
#include <math.h>
#include <stdint.h>

// ---------------------------------------------------------------------------
// MultiScaleDeformableAttention, fp32 in/out.
// GEMMs: mma.sync bf16 m16n8k16, 3-term compensation with register reuse
//   (A'=[Ah|Al] K=512; acc += Ah*Bh + Ah*Bl + Al*Bh).
// Round-9: BK=16 stages (20.5KB) -> 3-stage pipe fits 2 CTAs/SM (123KB smem),
// doubling resident warps to hide cp.async/barrier latency.
// Sampler: round-6 float4 version (best measured: ~165us).
// ---------------------------------------------------------------------------

#define NQ    20197
#define BSZ   2
#define EDIM  256
#define NLVL  4
#define MTOT  (BSZ * NQ)     // 40394

#define KP2   512            // [hi(256) | lo(256)] row stride
#define BK    16
#define NKIT  16             // 256 / BK
#define APAD3 40             // stage row elems: 16 h + 16 l + 8 pad
#define TILE_E (128 * APAD3) // 5120 elems per operand per stage
#define STAGE_B (2 * TILE_E * 2)     // 20480 B per stage (A + B)
#define SMEM_GEMM (3 * STAGE_B)      // 61440 B -> 2 CTAs/SM

#define QASTR 384            // fused SO|AW output row stride

// ------------------------------- scratch ------------------------------------
__device__ float g_V  [MTOT * EDIM];
__device__ float g_QA [(size_t)MTOT * QASTR];   // [SO(256) | AWL(128)]
__device__ __nv_bfloat16 g_Aval[(size_t)MTOT * KP2];
__device__ __nv_bfloat16 g_Aq  [(size_t)MTOT * KP2];
__device__ __nv_bfloat16 g_Atmp[(size_t)MTOT * KP2];
__device__ __nv_bfloat16 g_Bv [256 * KP2];
__device__ __nv_bfloat16 g_Bqa[QASTR * KP2];
__device__ __nv_bfloat16 g_Bo [256 * KP2];
__device__ float g_biasQA[QASTR];

// -------------------------- small PTX helpers -------------------------------
__device__ __forceinline__ uint32_t smem_u32(const void* p) {
    uint32_t a;
    asm("{ .reg .u64 t; cvta.to.shared.u64 t, %1; cvt.u32.u64 %0, t; }"
        : "=r"(a) : "l"(p));
    return a;
}
__device__ __forceinline__ void cp_async16(uint32_t dst, const void* src) {
    asm volatile("cp.async.cg.shared.global [%0], [%1], 16;"
                 :: "r"(dst), "l"(src) : "memory");
}
__device__ __forceinline__ void cp_commit() {
    asm volatile("cp.async.commit_group;" ::: "memory");
}
template <int N>
__device__ __forceinline__ void cp_wait() {
    asm volatile("cp.async.wait_group %0;" :: "n"(N) : "memory");
}
__device__ __forceinline__ void ldmatrix_x4(uint32_t* r, uint32_t addr) {
    asm volatile("ldmatrix.sync.aligned.m8n8.x4.shared.b16 {%0,%1,%2,%3}, [%4];"
                 : "=r"(r[0]), "=r"(r[1]), "=r"(r[2]), "=r"(r[3]) : "r"(addr));
}
__device__ __forceinline__ void mma_bf16(float* c, const uint32_t* a,
                                         uint32_t b0, uint32_t b1) {
    asm volatile(
        "mma.sync.aligned.m16n8k16.row.col.f32.bf16.bf16.f32 "
        "{%0,%1,%2,%3}, {%4,%5,%6,%7}, {%8,%9}, {%0,%1,%2,%3};"
        : "+f"(c[0]), "+f"(c[1]), "+f"(c[2]), "+f"(c[3])
        : "r"(a[0]), "r"(a[1]), "r"(a[2]), "r"(a[3]), "r"(b0), "r"(b1));
}

// ---------------------------------------------------------------------------
// fp32 activation -> bf16 [hi(256) | lo(256)], row stride KP2
// ---------------------------------------------------------------------------
__global__ __launch_bounds__(256) void split_cat(
    const float* __restrict__ x, __nv_bfloat16* __restrict__ out, int n4)
{
    const int i = blockIdx.x * 256 + threadIdx.x;
    if (i >= n4) return;
    const float4 v = ((const float4*)x)[i];
    const int row = i >> 6;
    const int c4  = (i & 63) << 2;
    __nv_bfloat16 h[4], l[4];
    const float f[4] = {v.x, v.y, v.z, v.w};
#pragma unroll
    for (int k = 0; k < 4; k++) {
        h[k] = __float2bfloat16(f[k]);
        l[k] = __float2bfloat16(f[k] - __bfloat162float(h[k]));
    }
    __nv_bfloat16* base = out + (size_t)row * KP2 + c4;
    *(uint2*)(base)       = *(const uint2*)h;
    *(uint2*)(base + 256) = *(const uint2*)l;
}

// ---------------------------------------------------------------------------
// One-shot weight prep: W[K=256,N] -> B't[N][KP2]=[h|l] transposed + bias cat.
// ---------------------------------------------------------------------------
__global__ __launch_bounds__(256) void prep_weights(
    const float* __restrict__ Wv,  const float* __restrict__ Wso,
    const float* __restrict__ Waw, const float* __restrict__ Wo,
    const float* __restrict__ bso, const float* __restrict__ baw)
{
    const int idx = blockIdx.x * 256 + threadIdx.x;
    const float* W;
    __nv_bfloat16* Bt;
    int li, N, nofs = 0;
    if (idx < 65536)        { W = Wv;  Bt = g_Bv;  li = idx;          N = 256; }
    else if (idx < 131072)  { W = Wso; Bt = g_Bqa; li = idx - 65536;  N = 256; }
    else if (idx < 163840)  { W = Waw; Bt = g_Bqa; li = idx - 131072; N = 128; nofs = 256; }
    else if (idx < 229376)  { W = Wo;  Bt = g_Bo;  li = idx - 163840; N = 256; }
    else {
        const int i = idx - 229376;
        if (i < 256)      g_biasQA[i] = bso[i];
        else if (i < 384) g_biasQA[i] = baw[i - 256];
        return;
    }
    const int k = li / N, n = li % N;
    const float v = W[li];
    const __nv_bfloat16 h = __float2bfloat16(v);
    const __nv_bfloat16 l = __float2bfloat16(v - __bfloat162float(h));
    __nv_bfloat16* base = Bt + (size_t)(n + nofs) * KP2 + k;
    base[0]   = h;
    base[256] = l;
}

// ---------------------------------------------------------------------------
// bf16 mma GEMM, register-reuse 3-term compensation. BK=16 per stage.
// BM=128, BN=128, 8 warps (4x2), warp tile 32x64. 3-stage, 2 CTAs/SM.
// ---------------------------------------------------------------------------
__global__ __launch_bounds__(256, 2) void gemm_mma(
    const __nv_bfloat16* __restrict__ A, const __nv_bfloat16* __restrict__ Bt,
    const float* __restrict__ bias, const float* __restrict__ res,
    float* __restrict__ C, int M, int N)
{
    extern __shared__ __align__(16) char smem[];
    const uint32_t sBase = smem_u32(smem);

    const int tid  = threadIdx.x;
    const int lane = tid & 31;
    const int wid  = tid >> 5;
    const int wm   = wid & 3;
    const int wn   = wid >> 2;
    const int m0   = blockIdx.x * 128;
    const int n0   = blockIdx.y * 128;

    // stage row: [h(16) | l(16) | pad(8)] elems. 512 chunk16 per operand.
    auto load_stage = [&](int stg, int kt) {
        const int kbase = kt * BK;
        const uint32_t sA = sBase + (uint32_t)stg * STAGE_B;
        const uint32_t sB = sA + TILE_E * 2;
#pragma unroll
        for (int it = 0; it < 2; it++) {
            const int c   = tid + it * 256;          // 0..511
            const int row = c >> 2;
            const int seg = (c & 3) << 3;            // 0,8,16,24 elems
            const int gcol = (seg < 16) ? (kbase + seg) : (256 + kbase + seg - 16);
            const uint32_t soff = (uint32_t)(row * APAD3 + seg) * 2;
            const int ar = min(m0 + row, M - 1);
            cp_async16(sA + soff, A + (size_t)ar * KP2 + gcol);
            cp_async16(sB + soff, Bt + (size_t)(n0 + row) * KP2 + gcol);
        }
    };

    float acc[2][8][4];
#pragma unroll
    for (int mi = 0; mi < 2; mi++)
#pragma unroll
        for (int nj = 0; nj < 8; nj++)
#pragma unroll
            for (int k = 0; k < 4; k++) acc[mi][nj][k] = 0.f;

    load_stage(0, 0); cp_commit();
    load_stage(1, 1); cp_commit();

    int stg = 0;
#pragma unroll 1
    for (int kt = 0; kt < NKIT; kt++) {
        cp_wait<1>();
        __syncthreads();

        if (kt + 2 < NKIT) load_stage((stg + 2) % 3, kt + 2);
        cp_commit();   // empty groups at tail keep wait<1> accounting exact

        const uint32_t aB = sBase + (uint32_t)stg * STAGE_B;
        const uint32_t bB = aB + TILE_E * 2;

        uint32_t ah[2][4], al[2][4];
#pragma unroll
        for (int mi = 0; mi < 2; mi++) {
            const int row = wm * 32 + mi * 16 + (lane & 15);
            const int col = (lane >> 4) << 3;        // 0 or 8
            ldmatrix_x4(ah[mi], aB + (uint32_t)(row * APAD3 + col) * 2);
            ldmatrix_x4(al[mi], aB + (uint32_t)(row * APAD3 + 16 + col) * 2);
        }
#pragma unroll
        for (int njp = 0; njp < 4; njp++) {
            const int row = wn * 64 + njp * 16 + ((lane >> 4) & 1) * 8 + (lane & 7);
            const int col = ((lane >> 3) & 1) * 8;
            uint32_t bh[4], bl[4];
            ldmatrix_x4(bh, bB + (uint32_t)(row * APAD3 + col) * 2);
            ldmatrix_x4(bl, bB + (uint32_t)(row * APAD3 + 16 + col) * 2);
#pragma unroll
            for (int mi = 0; mi < 2; mi++) {
                float* a0 = acc[mi][njp * 2];
                float* a1 = acc[mi][njp * 2 + 1];
                mma_bf16(a0, ah[mi], bh[0], bh[1]);   // Ah*Bh
                mma_bf16(a1, ah[mi], bh[2], bh[3]);
                mma_bf16(a0, ah[mi], bl[0], bl[1]);   // Ah*Bl
                mma_bf16(a1, ah[mi], bl[2], bl[3]);
                mma_bf16(a0, al[mi], bh[0], bh[1]);   // Al*Bh
                mma_bf16(a1, al[mi], bh[2], bh[3]);
            }
        }
        stg = (stg + 1) % 3;
    }

    // ---- epilogue ----
#pragma unroll
    for (int mi = 0; mi < 2; mi++) {
#pragma unroll
        for (int nj = 0; nj < 8; nj++) {
            const int col = n0 + wn * 64 + nj * 8 + (lane & 3) * 2;
            const int r0  = m0 + wm * 32 + mi * 16 + (lane >> 2);
            const int r1  = r0 + 8;
            const float b0 = bias[col], b1 = bias[col + 1];
            if (r0 < M) {
                float2 o = make_float2(acc[mi][nj][0] + b0, acc[mi][nj][1] + b1);
                if (res) {
                    const float2 rv = *(const float2*)(res + (size_t)r0 * N + col);
                    o.x += rv.x; o.y += rv.y;
                }
                *(float2*)(C + (size_t)r0 * N + col) = o;
            }
            if (r1 < M) {
                float2 o = make_float2(acc[mi][nj][2] + b0, acc[mi][nj][3] + b1);
                if (res) {
                    const float2 rv = *(const float2*)(res + (size_t)r1 * N + col);
                    o.x += rv.x; o.y += rv.y;
                }
                *(float2*)(C + (size_t)r1 * N + col) = o;
            }
        }
    }
}

// ---------------------------------------------------------------------------
// Sampler (round-6 float4 version — best measured). Block = 4 queries.
// ---------------------------------------------------------------------------
__global__ __launch_bounds__(256) void msda_sample4(
    const float* __restrict__ V, const float* __restrict__ QA,
    const float* __restrict__ refp,
    const int* __restrict__ shapes, const int* __restrict__ starts,
    __nv_bfloat16* __restrict__ outCat, int M)
{
    __shared__ int4   sOff[4][16][8];
    __shared__ float4 sW  [4][16][8];

    const int tid = threadIdx.x;

    // Phase A
    {
        const int wi  = tid << 1;
        const int bqL = wi >> 7;
        const int h   = (wi >> 4) & 7;
        const int pt0 = wi & 15;
        int bq = blockIdx.x * 4 + bqL;
        bq = min(bq, M - 1);

        const float2 lg = *(const float2*)(QA + (size_t)bq * QASTR + 256 + h * 16 + pt0);
        float mx = fmaxf(lg.x, lg.y);
#pragma unroll
        for (int off = 4; off; off >>= 1)
            mx = fmaxf(mx, __shfl_xor_sync(0xffffffffu, mx, off));
        const float e0 = expf(lg.x - mx);
        const float e1 = expf(lg.y - mx);
        float sm = e0 + e1;
#pragma unroll
        for (int off = 4; off; off >>= 1)
            sm += __shfl_xor_sync(0xffffffffu, sm, off);
        const float inv = 1.f / sm;

        const int l = pt0 >> 2;
        const int H = shapes[2 * l + 0];
        const int W = shapes[2 * l + 1];
        const int st = starts[l];
        const float2 rp = *(const float2*)(refp + ((size_t)bq * NLVL + l) * 2);
        const float4 so = *(const float4*)(QA + (size_t)bq * QASTR + h * 32 + pt0 * 2);

#pragma unroll
        for (int k = 0; k < 2; k++) {
            const int pt = pt0 + k;
            const float aw  = (k ? e1 : e0) * inv;
            const float sox = k ? so.z : so.x;
            const float soy = k ? so.w : so.y;

            const float x = fmaf(rp.x, (float)W, sox) - 0.5f;
            const float y = fmaf(rp.y, (float)H, soy) - 0.5f;
            const float xf = floorf(x), yf = floorf(y);
            const int x0 = (int)xf, y0 = (int)yf;
            const float wx1 = x - xf, wx0 = 1.f - wx1;
            const float wy1 = y - yf, wy0 = 1.f - wy1;

            const bool vx0 = (x0 >= 0) && (x0 < W);
            const bool vx1 = (x0 + 1 >= 0) && (x0 + 1 < W);
            const bool vy0 = (y0 >= 0) && (y0 < H);
            const bool vy1 = (y0 + 1 >= 0) && (y0 + 1 < H);

            const int cx0 = max(0, min(x0,     W - 1));
            const int cx1 = max(0, min(x0 + 1, W - 1));
            const int cy0 = max(0, min(y0,     H - 1));
            const int cy1 = max(0, min(y0 + 1, H - 1));

            int4 o;
            o.x = st + cy0 * W + cx0;
            o.y = st + cy0 * W + cx1;
            o.z = st + cy1 * W + cx0;
            o.w = st + cy1 * W + cx1;

            float4 w4;
            w4.x = (vx0 && vy0) ? wx0 * wy0 * aw : 0.f;
            w4.y = (vx1 && vy0) ? wx1 * wy0 * aw : 0.f;
            w4.z = (vx0 && vy1) ? wx0 * wy1 * aw : 0.f;
            w4.w = (vx1 && vy1) ? wx1 * wy1 * aw : 0.f;

            sOff[bqL][pt][h] = o;
            sW  [bqL][pt][h] = w4;
        }
    }
    __syncthreads();

    // Phase B
    const int warpId = tid >> 5;
    const int lane   = tid & 31;
    const int bqL    = warpId >> 1;
    const int h      = ((warpId & 1) << 2) + (lane >> 3);
    const int c4     = lane & 7;
    const int bq     = blockIdx.x * 4 + bqL;
    if (bq >= M) return;
    const int b = bq / NQ;

    const float* vb = V + (size_t)b * NQ * EDIM + h * 32 + c4 * 4;

    float4 acc = make_float4(0.f, 0.f, 0.f, 0.f);
#pragma unroll
    for (int pt = 0; pt < 16; pt++) {
        const int4   o = sOff[bqL][pt][h];
        const float4 w = sW  [bqL][pt][h];

        const float4 v0 = *(const float4*)(vb + (size_t)o.x * EDIM);
        const float4 v1 = *(const float4*)(vb + (size_t)o.y * EDIM);
        const float4 v2 = *(const float4*)(vb + (size_t)o.z * EDIM);
        const float4 v3 = *(const float4*)(vb + (size_t)o.w * EDIM);

        acc.x = fmaf(w.x, v0.x, acc.x); acc.y = fmaf(w.x, v0.y, acc.y);
        acc.z = fmaf(w.x, v0.z, acc.z); acc.w = fmaf(w.x, v0.w, acc.w);
        acc.x = fmaf(w.y, v1.x, acc.x); acc.y = fmaf(w.y, v1.y, acc.y);
        acc.z = fmaf(w.y, v1.z, acc.z); acc.w = fmaf(w.y, v1.w, acc.w);
        acc.x = fmaf(w.z, v2.x, acc.x); acc.y = fmaf(w.z, v2.y, acc.y);
        acc.z = fmaf(w.z, v2.z, acc.z); acc.w = fmaf(w.z, v2.w, acc.w);
        acc.x = fmaf(w.w, v3.x, acc.x); acc.y = fmaf(w.w, v3.y, acc.y);
        acc.z = fmaf(w.w, v3.z, acc.z); acc.w = fmaf(w.w, v3.w, acc.w);
    }

    __nv_bfloat16 hh[4], ll[4];
    const float f[4] = {acc.x, acc.y, acc.z, acc.w};
#pragma unroll
    for (int k = 0; k < 4; k++) {
        hh[k] = __float2bfloat16(f[k]);
        ll[k] = __float2bfloat16(f[k] - __bfloat162float(hh[k]));
    }
    __nv_bfloat16* base = outCat + (size_t)bq * KP2 + h * 32 + c4 * 4;
    *(uint2*)(base)       = *(const uint2*)hh;
    *(uint2*)(base + 256) = *(const uint2*)ll;
}

// ---------------------------------------------------------------------------
// Launch
// ---------------------------------------------------------------------------
extern "C" void kernel_launch(void* const* d_in, const int* in_sizes, int n_in,
                              void* d_out, int out_size)
{
    const float* query  = (const float*)d_in[0];
    const float* value  = (const float*)d_in[1];
    const float* refp   = (const float*)d_in[2];
    const int*   shapes = (const int*)  d_in[3];
    const int*   starts = (const int*)  d_in[4];
    const float* Wv  = (const float*)d_in[5];
    const float* bv  = (const float*)d_in[6];
    const float* Wso = (const float*)d_in[7];
    const float* bso = (const float*)d_in[8];
    const float* Waw = (const float*)d_in[9];
    const float* baw = (const float*)d_in[10];
    const float* Wo  = (const float*)d_in[11];
    const float* bo  = (const float*)d_in[12];
    float* out = (float*)d_out;

    const int M = in_sizes[0] / EDIM;   // 40394

    float *pV, *pQA, *pBiasQA;
    __nv_bfloat16 *pAval, *pAq, *pAtmp, *pBv, *pBqa, *pBo;
    cudaGetSymbolAddress((void**)&pV,     g_V);
    cudaGetSymbolAddress((void**)&pQA,    g_QA);
    cudaGetSymbolAddress((void**)&pBiasQA,g_biasQA);
    cudaGetSymbolAddress((void**)&pAval,  g_Aval);
    cudaGetSymbolAddress((void**)&pAq,    g_Aq);
    cudaGetSymbolAddress((void**)&pAtmp,  g_Atmp);
    cudaGetSymbolAddress((void**)&pBv,    g_Bv);
    cudaGetSymbolAddress((void**)&pBqa,   g_Bqa);
    cudaGetSymbolAddress((void**)&pBo,    g_Bo);

    cudaFuncSetAttribute(gemm_mma, cudaFuncAttributeMaxDynamicSharedMemorySize, SMEM_GEMM);

    const int n4 = M * (EDIM / 4);
    const int cvtBlocks = (n4 + 255) / 256;
    const int mTiles = (M + 127) / 128;
    const dim3 g256(mTiles, 2);
    const dim3 g384(mTiles, 3);

    split_cat<<<cvtBlocks, 256>>>(value, pAval, n4);
    split_cat<<<cvtBlocks, 256>>>(query, pAq,   n4);
    prep_weights<<<(229760 + 255) / 256, 256>>>(Wv, Wso, Waw, Wo, bso, baw);

    gemm_mma<<<g256, 256, SMEM_GEMM>>>(pAval, pBv,  bv,      nullptr, pV,  M, 256);
    gemm_mma<<<g384, 256, SMEM_GEMM>>>(pAq,   pBqa, pBiasQA, nullptr, pQA, M, QASTR);
    msda_sample4<<<(M + 3) / 4, 256>>>(pV, pQA, refp, shapes, starts, pAtmp, M);
    gemm_mma<<<g256, 256, SMEM_GEMM>>>(pAtmp, pBo,  bo,      query,   out, M, 256);
}

// round 10
// speedup vs baseline: 1.1091x; 1.1091x over previous
#include <cuda_runtime.h>
#include <cuda_bf16.h>
#include <math.h>
#include <stdint.h>

// ---------------------------------------------------------------------------
// MultiScaleDeformableAttention, fp32 in/out.
// GEMMs: mma.sync bf16 m16n8k16, 3-term compensation with register reuse
//   (A'=[Ah|Al] K=512; acc += Ah*Bh + Ah*Bl + Al*Bh).  [R6 config restored]
// Round-10: launch consolidation — one conversion kernel, one fused
// value+QA GEMM launch (tail amortization), sampler/output GEMM unchanged.
// ---------------------------------------------------------------------------

#define NQ    20197
#define BSZ   2
#define EDIM  256
#define NLVL  4
#define MTOT  (BSZ * NQ)     // 40394

#define KP2   512            // [hi(256) | lo(256)] row stride
#define BK    32
#define NKIT  8              // 256 / BK
#define APAD2 72             // stage row elems (64 data + 8 pad)
#define TILE_E (128 * APAD2)
#define STAGE_B (2 * TILE_E * 2)     // 36864 B per stage (A + B)
#define SMEM_GEMM (3 * STAGE_B)      // 110592 B -> 2 CTAs/SM

#define QASTR 384            // fused SO|AW output row stride

// ------------------------------- scratch ------------------------------------
__device__ float g_V  [MTOT * EDIM];
__device__ float g_QA [(size_t)MTOT * QASTR];   // [SO(256) | AWL(128)]
__device__ __nv_bfloat16 g_Aval[(size_t)MTOT * KP2];
__device__ __nv_bfloat16 g_Aq  [(size_t)MTOT * KP2];
__device__ __nv_bfloat16 g_Atmp[(size_t)MTOT * KP2];
__device__ __nv_bfloat16 g_Bv [256 * KP2];
__device__ __nv_bfloat16 g_Bqa[QASTR * KP2];
__device__ __nv_bfloat16 g_Bo [256 * KP2];
__device__ float g_biasQA[QASTR];

// -------------------------- small PTX helpers -------------------------------
__device__ __forceinline__ uint32_t smem_u32(const void* p) {
    uint32_t a;
    asm("{ .reg .u64 t; cvta.to.shared.u64 t, %1; cvt.u32.u64 %0, t; }"
        : "=r"(a) : "l"(p));
    return a;
}
__device__ __forceinline__ void cp_async16(uint32_t dst, const void* src) {
    asm volatile("cp.async.cg.shared.global [%0], [%1], 16;"
                 :: "r"(dst), "l"(src) : "memory");
}
__device__ __forceinline__ void cp_commit() {
    asm volatile("cp.async.commit_group;" ::: "memory");
}
template <int N>
__device__ __forceinline__ void cp_wait() {
    asm volatile("cp.async.wait_group %0;" :: "n"(N) : "memory");
}
__device__ __forceinline__ void ldmatrix_x4(uint32_t* r, uint32_t addr) {
    asm volatile("ldmatrix.sync.aligned.m8n8.x4.shared.b16 {%0,%1,%2,%3}, [%4];"
                 : "=r"(r[0]), "=r"(r[1]), "=r"(r[2]), "=r"(r[3]) : "r"(addr));
}
__device__ __forceinline__ void mma_bf16(float* c, const uint32_t* a,
                                         uint32_t b0, uint32_t b1) {
    asm volatile(
        "mma.sync.aligned.m16n8k16.row.col.f32.bf16.bf16.f32 "
        "{%0,%1,%2,%3}, {%4,%5,%6,%7}, {%8,%9}, {%0,%1,%2,%3};"
        : "+f"(c[0]), "+f"(c[1]), "+f"(c[2]), "+f"(c[3])
        : "r"(a[0]), "r"(a[1]), "r"(a[2]), "r"(a[3]), "r"(b0), "r"(b1));
}

// ---------------------------------------------------------------------------
// Merged conversion kernel:
//   blocks [0, cvtB)        : value -> g_Aval  ([hi|lo] bf16, stride KP2)
//   blocks [cvtB, 2*cvtB)   : query -> g_Aq
//   blocks [2*cvtB, ...)    : weights transposed splits + bias concat
// ---------------------------------------------------------------------------
__global__ __launch_bounds__(256) void prep_all(
    const float* __restrict__ value, const float* __restrict__ query,
    const float* __restrict__ Wv,  const float* __restrict__ Wso,
    const float* __restrict__ Waw, const float* __restrict__ Wo,
    const float* __restrict__ bso, const float* __restrict__ baw,
    int n4, int cvtB)
{
    const int bx  = blockIdx.x;
    const int tid = threadIdx.x;

    if (bx < 2 * cvtB) {
        const float* x = (bx < cvtB) ? value : query;
        __nv_bfloat16* out = (bx < cvtB) ? g_Aval : g_Aq;
        const int i = (bx % cvtB) * 256 + tid;
        if (i >= n4) return;
        const float4 v = ((const float4*)x)[i];
        const int row = i >> 6;
        const int c4  = (i & 63) << 2;
        __nv_bfloat16 h[4], l[4];
        const float f[4] = {v.x, v.y, v.z, v.w};
#pragma unroll
        for (int k = 0; k < 4; k++) {
            h[k] = __float2bfloat16(f[k]);
            l[k] = __float2bfloat16(f[k] - __bfloat162float(h[k]));
        }
        __nv_bfloat16* base = out + (size_t)row * KP2 + c4;
        *(uint2*)(base)       = *(const uint2*)h;
        *(uint2*)(base + 256) = *(const uint2*)l;
        return;
    }

    const int idx = (bx - 2 * cvtB) * 256 + tid;
    const float* W;
    __nv_bfloat16* Bt;
    int li, N, nofs = 0;
    if (idx < 65536)        { W = Wv;  Bt = g_Bv;  li = idx;          N = 256; }
    else if (idx < 131072)  { W = Wso; Bt = g_Bqa; li = idx - 65536;  N = 256; }
    else if (idx < 163840)  { W = Waw; Bt = g_Bqa; li = idx - 131072; N = 128; nofs = 256; }
    else if (idx < 229376)  { W = Wo;  Bt = g_Bo;  li = idx - 163840; N = 256; }
    else {
        const int i = idx - 229376;
        if (i < 256)      g_biasQA[i] = bso[i];
        else if (i < 384) g_biasQA[i] = baw[i - 256];
        return;
    }
    const int k = li / N, n = li % N;
    const float v = W[li];
    const __nv_bfloat16 h = __float2bfloat16(v);
    const __nv_bfloat16 l = __float2bfloat16(v - __bfloat162float(h));
    __nv_bfloat16* base = Bt + (size_t)(n + nofs) * KP2 + k;
    base[0]   = h;
    base[256] = l;
}

// ---------------------------------------------------------------------------
// GEMM core (R6 config): BM=128, BN=128, BK=32, 8 warps (4x2), warp 32x64,
// 3-stage cp.async, register-reuse 3-term compensation.
// ---------------------------------------------------------------------------
__device__ __forceinline__ void gemm_body(
    const __nv_bfloat16* __restrict__ A, const __nv_bfloat16* __restrict__ Bt,
    const float* __restrict__ bias, const float* __restrict__ res,
    float* __restrict__ C, int M, int N, int m0, int n0, char* smem)
{
    const uint32_t sBase = smem_u32(smem);
    const int tid  = threadIdx.x;
    const int lane = tid & 31;
    const int wid  = tid >> 5;
    const int wm   = wid & 3;
    const int wn   = wid >> 2;

    auto load_stage = [&](int stg, int kt) {
        const int kbase = kt * BK;
        const uint32_t sA = sBase + (uint32_t)stg * STAGE_B;
        const uint32_t sB = sA + TILE_E * 2;
#pragma unroll
        for (int it = 0; it < 4; it++) {
            const int c   = tid + it * 256;
            const int row = c >> 3;
            const int seg = (c & 7) << 3;
            const int gcol = (seg < 32) ? (kbase + seg) : (256 + kbase + seg - 32);
            const uint32_t soff = (uint32_t)(row * APAD2 + seg) * 2;
            const int ar = min(m0 + row, M - 1);
            cp_async16(sA + soff, A + (size_t)ar * KP2 + gcol);
            cp_async16(sB + soff, Bt + (size_t)(n0 + row) * KP2 + gcol);
        }
    };

    float acc[2][8][4];
#pragma unroll
    for (int mi = 0; mi < 2; mi++)
#pragma unroll
        for (int nj = 0; nj < 8; nj++)
#pragma unroll
            for (int k = 0; k < 4; k++) acc[mi][nj][k] = 0.f;

    load_stage(0, 0); cp_commit();
    load_stage(1, 1); cp_commit();

    int stg = 0;
#pragma unroll 1
    for (int kt = 0; kt < NKIT; kt++) {
        cp_wait<1>();
        __syncthreads();

        if (kt + 2 < NKIT) load_stage((stg + 2) % 3, kt + 2);
        cp_commit();   // empty groups at tail keep wait<1> exact

        const uint32_t aB = sBase + (uint32_t)stg * STAGE_B;
        const uint32_t bB = aB + TILE_E * 2;

#pragma unroll
        for (int ks = 0; ks < 2; ks++) {
            uint32_t ah[2][4], al[2][4];
#pragma unroll
            for (int mi = 0; mi < 2; mi++) {
                const int row = wm * 32 + mi * 16 + (lane & 15);
                const int col = ks * 16 + ((lane >> 4) << 3);
                ldmatrix_x4(ah[mi], aB + (uint32_t)(row * APAD2 + col) * 2);
                ldmatrix_x4(al[mi], aB + (uint32_t)(row * APAD2 + 32 + col) * 2);
            }
#pragma unroll
            for (int njp = 0; njp < 4; njp++) {
                const int row = wn * 64 + njp * 16 + ((lane >> 4) & 1) * 8 + (lane & 7);
                const int col = ks * 16 + ((lane >> 3) & 1) * 8;
                uint32_t bh[4], bl[4];
                ldmatrix_x4(bh, bB + (uint32_t)(row * APAD2 + col) * 2);
                ldmatrix_x4(bl, bB + (uint32_t)(row * APAD2 + 32 + col) * 2);
#pragma unroll
                for (int mi = 0; mi < 2; mi++) {
                    float* a0 = acc[mi][njp * 2];
                    float* a1 = acc[mi][njp * 2 + 1];
                    mma_bf16(a0, ah[mi], bh[0], bh[1]);
                    mma_bf16(a1, ah[mi], bh[2], bh[3]);
                    mma_bf16(a0, ah[mi], bl[0], bl[1]);
                    mma_bf16(a1, ah[mi], bl[2], bl[3]);
                    mma_bf16(a0, al[mi], bh[0], bh[1]);
                    mma_bf16(a1, al[mi], bh[2], bh[3]);
                }
            }
        }
        stg = (stg + 1) % 3;
    }

#pragma unroll
    for (int mi = 0; mi < 2; mi++) {
#pragma unroll
        for (int nj = 0; nj < 8; nj++) {
            const int col = n0 + wn * 64 + nj * 8 + (lane & 3) * 2;
            const int r0  = m0 + wm * 32 + mi * 16 + (lane >> 2);
            const int r1  = r0 + 8;
            const float b0 = bias[col], b1 = bias[col + 1];
            if (r0 < M) {
                float2 o = make_float2(acc[mi][nj][0] + b0, acc[mi][nj][1] + b1);
                if (res) {
                    const float2 rv = *(const float2*)(res + (size_t)r0 * N + col);
                    o.x += rv.x; o.y += rv.y;
                }
                *(float2*)(C + (size_t)r0 * N + col) = o;
            }
            if (r1 < M) {
                float2 o = make_float2(acc[mi][nj][2] + b0, acc[mi][nj][3] + b1);
                if (res) {
                    const float2 rv = *(const float2*)(res + (size_t)r1 * N + col);
                    o.x += rv.x; o.y += rv.y;
                }
                *(float2*)(C + (size_t)r1 * N + col) = o;
            }
        }
    }
}

// Fused value+QA GEMM: blockIdx.y 0-1 -> value (N=256), 2-4 -> QA (N=384).
__global__ __launch_bounds__(256, 2) void gemm_vqa(
    const __nv_bfloat16* __restrict__ Av, const __nv_bfloat16* __restrict__ Bv,
    const float* __restrict__ bv, float* __restrict__ Cv,
    const __nv_bfloat16* __restrict__ Aq, const __nv_bfloat16* __restrict__ Bqa,
    const float* __restrict__ bqa, float* __restrict__ Cqa, int M)
{
    extern __shared__ __align__(16) char smem[];
    const int y = blockIdx.y;
    const int m0 = blockIdx.x * 128;
    if (y < 2)
        gemm_body(Av, Bv, bv, nullptr, Cv, M, 256, m0, y * 128, smem);
    else
        gemm_body(Aq, Bqa, bqa, nullptr, Cqa, M, QASTR, m0, (y - 2) * 128, smem);
}

// Output GEMM (bias + residual epilogue).
__global__ __launch_bounds__(256, 2) void gemm_out(
    const __nv_bfloat16* __restrict__ A, const __nv_bfloat16* __restrict__ Bt,
    const float* __restrict__ bias, const float* __restrict__ res,
    float* __restrict__ C, int M)
{
    extern __shared__ __align__(16) char smem[];
    gemm_body(A, Bt, bias, res, C, M, 256, blockIdx.x * 128, blockIdx.y * 128, smem);
}

// ---------------------------------------------------------------------------
// Sampler (round-6 float4 version — best measured). Block = 4 queries.
// ---------------------------------------------------------------------------
__global__ __launch_bounds__(256) void msda_sample4(
    const float* __restrict__ V, const float* __restrict__ QA,
    const float* __restrict__ refp,
    const int* __restrict__ shapes, const int* __restrict__ starts,
    __nv_bfloat16* __restrict__ outCat, int M)
{
    __shared__ int4   sOff[4][16][8];
    __shared__ float4 sW  [4][16][8];

    const int tid = threadIdx.x;

    // Phase A
    {
        const int wi  = tid << 1;
        const int bqL = wi >> 7;
        const int h   = (wi >> 4) & 7;
        const int pt0 = wi & 15;
        int bq = blockIdx.x * 4 + bqL;
        bq = min(bq, M - 1);

        const float2 lg = *(const float2*)(QA + (size_t)bq * QASTR + 256 + h * 16 + pt0);
        float mx = fmaxf(lg.x, lg.y);
#pragma unroll
        for (int off = 4; off; off >>= 1)
            mx = fmaxf(mx, __shfl_xor_sync(0xffffffffu, mx, off));
        const float e0 = expf(lg.x - mx);
        const float e1 = expf(lg.y - mx);
        float sm = e0 + e1;
#pragma unroll
        for (int off = 4; off; off >>= 1)
            sm += __shfl_xor_sync(0xffffffffu, sm, off);
        const float inv = 1.f / sm;

        const int l = pt0 >> 2;
        const int H = shapes[2 * l + 0];
        const int W = shapes[2 * l + 1];
        const int st = starts[l];
        const float2 rp = *(const float2*)(refp + ((size_t)bq * NLVL + l) * 2);
        const float4 so = *(const float4*)(QA + (size_t)bq * QASTR + h * 32 + pt0 * 2);

#pragma unroll
        for (int k = 0; k < 2; k++) {
            const int pt = pt0 + k;
            const float aw  = (k ? e1 : e0) * inv;
            const float sox = k ? so.z : so.x;
            const float soy = k ? so.w : so.y;

            const float x = fmaf(rp.x, (float)W, sox) - 0.5f;
            const float y = fmaf(rp.y, (float)H, soy) - 0.5f;
            const float xf = floorf(x), yf = floorf(y);
            const int x0 = (int)xf, y0 = (int)yf;
            const float wx1 = x - xf, wx0 = 1.f - wx1;
            const float wy1 = y - yf, wy0 = 1.f - wy1;

            const bool vx0 = (x0 >= 0) && (x0 < W);
            const bool vx1 = (x0 + 1 >= 0) && (x0 + 1 < W);
            const bool vy0 = (y0 >= 0) && (y0 < H);
            const bool vy1 = (y0 + 1 >= 0) && (y0 + 1 < H);

            const int cx0 = max(0, min(x0,     W - 1));
            const int cx1 = max(0, min(x0 + 1, W - 1));
            const int cy0 = max(0, min(y0,     H - 1));
            const int cy1 = max(0, min(y0 + 1, H - 1));

            int4 o;
            o.x = st + cy0 * W + cx0;
            o.y = st + cy0 * W + cx1;
            o.z = st + cy1 * W + cx0;
            o.w = st + cy1 * W + cx1;

            float4 w4;
            w4.x = (vx0 && vy0) ? wx0 * wy0 * aw : 0.f;
            w4.y = (vx1 && vy0) ? wx1 * wy0 * aw : 0.f;
            w4.z = (vx0 && vy1) ? wx0 * wy1 * aw : 0.f;
            w4.w = (vx1 && vy1) ? wx1 * wy1 * aw : 0.f;

            sOff[bqL][pt][h] = o;
            sW  [bqL][pt][h] = w4;
        }
    }
    __syncthreads();

    // Phase B
    const int warpId = tid >> 5;
    const int lane   = tid & 31;
    const int bqL    = warpId >> 1;
    const int h      = ((warpId & 1) << 2) + (lane >> 3);
    const int c4     = lane & 7;
    const int bq     = blockIdx.x * 4 + bqL;
    if (bq >= M) return;
    const int b = bq / NQ;

    const float* vb = V + (size_t)b * NQ * EDIM + h * 32 + c4 * 4;

    float4 acc = make_float4(0.f, 0.f, 0.f, 0.f);
#pragma unroll
    for (int pt = 0; pt < 16; pt++) {
        const int4   o = sOff[bqL][pt][h];
        const float4 w = sW  [bqL][pt][h];

        const float4 v0 = *(const float4*)(vb + (size_t)o.x * EDIM);
        const float4 v1 = *(const float4*)(vb + (size_t)o.y * EDIM);
        const float4 v2 = *(const float4*)(vb + (size_t)o.z * EDIM);
        const float4 v3 = *(const float4*)(vb + (size_t)o.w * EDIM);

        acc.x = fmaf(w.x, v0.x, acc.x); acc.y = fmaf(w.x, v0.y, acc.y);
        acc.z = fmaf(w.x, v0.z, acc.z); acc.w = fmaf(w.x, v0.w, acc.w);
        acc.x = fmaf(w.y, v1.x, acc.x); acc.y = fmaf(w.y, v1.y, acc.y);
        acc.z = fmaf(w.y, v1.z, acc.z); acc.w = fmaf(w.y, v1.w, acc.w);
        acc.x = fmaf(w.z, v2.x, acc.x); acc.y = fmaf(w.z, v2.y, acc.y);
        acc.z = fmaf(w.z, v2.z, acc.z); acc.w = fmaf(w.z, v2.w, acc.w);
        acc.x = fmaf(w.w, v3.x, acc.x); acc.y = fmaf(w.w, v3.y, acc.y);
        acc.z = fmaf(w.w, v3.z, acc.z); acc.w = fmaf(w.w, v3.w, acc.w);
    }

    __nv_bfloat16 hh[4], ll[4];
    const float f[4] = {acc.x, acc.y, acc.z, acc.w};
#pragma unroll
    for (int k = 0; k < 4; k++) {
        hh[k] = __float2bfloat16(f[k]);
        ll[k] = __float2bfloat16(f[k] - __bfloat162float(hh[k]));
    }
    __nv_bfloat16* base = outCat + (size_t)bq * KP2 + h * 32 + c4 * 4;
    *(uint2*)(base)       = *(const uint2*)hh;
    *(uint2*)(base + 256) = *(const uint2*)ll;
}

// ---------------------------------------------------------------------------
// Launch
// ---------------------------------------------------------------------------
extern "C" void kernel_launch(void* const* d_in, const int* in_sizes, int n_in,
                              void* d_out, int out_size)
{
    const float* query  = (const float*)d_in[0];
    const float* value  = (const float*)d_in[1];
    const float* refp   = (const float*)d_in[2];
    const int*   shapes = (const int*)  d_in[3];
    const int*   starts = (const int*)  d_in[4];
    const float* Wv  = (const float*)d_in[5];
    const float* bv  = (const float*)d_in[6];
    const float* Wso = (const float*)d_in[7];
    const float* bso = (const float*)d_in[8];
    const float* Waw = (const float*)d_in[9];
    const float* baw = (const float*)d_in[10];
    const float* Wo  = (const float*)d_in[11];
    const float* bo  = (const float*)d_in[12];
    float* out = (float*)d_out;

    const int M = in_sizes[0] / EDIM;   // 40394

    float *pV, *pQA, *pBiasQA;
    __nv_bfloat16 *pAval, *pAq, *pAtmp, *pBv, *pBqa, *pBo;
    cudaGetSymbolAddress((void**)&pV,     g_V);
    cudaGetSymbolAddress((void**)&pQA,    g_QA);
    cudaGetSymbolAddress((void**)&pBiasQA,g_biasQA);
    cudaGetSymbolAddress((void**)&pAval,  g_Aval);
    cudaGetSymbolAddress((void**)&pAq,    g_Aq);
    cudaGetSymbolAddress((void**)&pAtmp,  g_Atmp);
    cudaGetSymbolAddress((void**)&pBv,    g_Bv);
    cudaGetSymbolAddress((void**)&pBqa,   g_Bqa);
    cudaGetSymbolAddress((void**)&pBo,    g_Bo);

    cudaFuncSetAttribute(gemm_vqa, cudaFuncAttributeMaxDynamicSharedMemorySize, SMEM_GEMM);
    cudaFuncSetAttribute(gemm_out, cudaFuncAttributeMaxDynamicSharedMemorySize, SMEM_GEMM);

    const int n4 = M * (EDIM / 4);
    const int cvtB = (n4 + 255) / 256;
    const int wB   = (229760 + 255) / 256;
    const int mTiles = (M + 127) / 128;

    prep_all<<<2 * cvtB + wB, 256>>>(value, query, Wv, Wso, Waw, Wo, bso, baw,
                                     n4, cvtB);
    gemm_vqa<<<dim3(mTiles, 5), 256, SMEM_GEMM>>>(
        pAval, pBv, bv, pV, pAq, pBqa, pBiasQA, pQA, M);
    msda_sample4<<<(M + 3) / 4, 256>>>(pV, pQA, refp, shapes, starts, pAtmp, M);
    gemm_out<<<dim3(mTiles, 2), 256, SMEM_GEMM>>>(pAtmp, pBo, bo, query, out, M);
}

// round 11
// speedup vs baseline: 1.2282x; 1.1074x over previous
#include <cuda_runtime.h>
#include <cuda_bf16.h>
#include <math.h>
#include <stdint.h>

// ---------------------------------------------------------------------------
// MultiScaleDeformableAttention, fp32 in/out.
// GEMMs: mma.sync bf16 m16n8k16. Value & output GEMMs use 3-term error
// compensation (Ah*Bh + Ah*Bl + Al*Bh). Round-11: the QA GEMM (sampling
// offsets + attention logits) runs SINGLE-term (Ah*Bh) — error analysis shows
// its output-error contribution is ~1e-4, far under the 1e-3 gate.
// ---------------------------------------------------------------------------

#define NQ    20197
#define BSZ   2
#define EDIM  256
#define NLVL  4
#define MTOT  (BSZ * NQ)     // 40394

#define KP2   512            // [hi(256) | lo(256)] row stride
#define BK    32
#define NKIT  8              // 256 / BK
#define APAD2 72             // stage row elems (64 data + 8 pad)
#define TILE_E (128 * APAD2)
#define STAGE_B (2 * TILE_E * 2)     // 36864 B per stage (A + B)
#define SMEM_GEMM (3 * STAGE_B)      // 110592 B -> 2 CTAs/SM

#define QASTR 384            // fused SO|AW output row stride

// ------------------------------- scratch ------------------------------------
__device__ float g_V  [MTOT * EDIM];
__device__ float g_QA [(size_t)MTOT * QASTR];   // [SO(256) | AWL(128)]
__device__ __nv_bfloat16 g_Aval[(size_t)MTOT * KP2];
__device__ __nv_bfloat16 g_Aq  [(size_t)MTOT * KP2];
__device__ __nv_bfloat16 g_Atmp[(size_t)MTOT * KP2];
__device__ __nv_bfloat16 g_Bv [256 * KP2];
__device__ __nv_bfloat16 g_Bqa[QASTR * KP2];
__device__ __nv_bfloat16 g_Bo [256 * KP2];
__device__ float g_biasQA[QASTR];

// -------------------------- small PTX helpers -------------------------------
__device__ __forceinline__ uint32_t smem_u32(const void* p) {
    uint32_t a;
    asm("{ .reg .u64 t; cvta.to.shared.u64 t, %1; cvt.u32.u64 %0, t; }"
        : "=r"(a) : "l"(p));
    return a;
}
__device__ __forceinline__ void cp_async16(uint32_t dst, const void* src) {
    asm volatile("cp.async.cg.shared.global [%0], [%1], 16;"
                 :: "r"(dst), "l"(src) : "memory");
}
__device__ __forceinline__ void cp_commit() {
    asm volatile("cp.async.commit_group;" ::: "memory");
}
template <int N>
__device__ __forceinline__ void cp_wait() {
    asm volatile("cp.async.wait_group %0;" :: "n"(N) : "memory");
}
__device__ __forceinline__ void ldmatrix_x4(uint32_t* r, uint32_t addr) {
    asm volatile("ldmatrix.sync.aligned.m8n8.x4.shared.b16 {%0,%1,%2,%3}, [%4];"
                 : "=r"(r[0]), "=r"(r[1]), "=r"(r[2]), "=r"(r[3]) : "r"(addr));
}
__device__ __forceinline__ void mma_bf16(float* c, const uint32_t* a,
                                         uint32_t b0, uint32_t b1) {
    asm volatile(
        "mma.sync.aligned.m16n8k16.row.col.f32.bf16.bf16.f32 "
        "{%0,%1,%2,%3}, {%4,%5,%6,%7}, {%8,%9}, {%0,%1,%2,%3};"
        : "+f"(c[0]), "+f"(c[1]), "+f"(c[2]), "+f"(c[3])
        : "r"(a[0]), "r"(a[1]), "r"(a[2]), "r"(a[3]), "r"(b0), "r"(b1));
}

// ---------------------------------------------------------------------------
// Merged conversion kernel (unchanged from R10).
// ---------------------------------------------------------------------------
__global__ __launch_bounds__(256) void prep_all(
    const float* __restrict__ value, const float* __restrict__ query,
    const float* __restrict__ Wv,  const float* __restrict__ Wso,
    const float* __restrict__ Waw, const float* __restrict__ Wo,
    const float* __restrict__ bso, const float* __restrict__ baw,
    int n4, int cvtB)
{
    const int bx  = blockIdx.x;
    const int tid = threadIdx.x;

    if (bx < 2 * cvtB) {
        const float* x = (bx < cvtB) ? value : query;
        __nv_bfloat16* out = (bx < cvtB) ? g_Aval : g_Aq;
        const int i = (bx % cvtB) * 256 + tid;
        if (i >= n4) return;
        const float4 v = ((const float4*)x)[i];
        const int row = i >> 6;
        const int c4  = (i & 63) << 2;
        __nv_bfloat16 h[4], l[4];
        const float f[4] = {v.x, v.y, v.z, v.w};
#pragma unroll
        for (int k = 0; k < 4; k++) {
            h[k] = __float2bfloat16(f[k]);
            l[k] = __float2bfloat16(f[k] - __bfloat162float(h[k]));
        }
        __nv_bfloat16* base = out + (size_t)row * KP2 + c4;
        *(uint2*)(base)       = *(const uint2*)h;
        *(uint2*)(base + 256) = *(const uint2*)l;
        return;
    }

    const int idx = (bx - 2 * cvtB) * 256 + tid;
    const float* W;
    __nv_bfloat16* Bt;
    int li, N, nofs = 0;
    if (idx < 65536)        { W = Wv;  Bt = g_Bv;  li = idx;          N = 256; }
    else if (idx < 131072)  { W = Wso; Bt = g_Bqa; li = idx - 65536;  N = 256; }
    else if (idx < 163840)  { W = Waw; Bt = g_Bqa; li = idx - 131072; N = 128; nofs = 256; }
    else if (idx < 229376)  { W = Wo;  Bt = g_Bo;  li = idx - 163840; N = 256; }
    else {
        const int i = idx - 229376;
        if (i < 256)      g_biasQA[i] = bso[i];
        else if (i < 384) g_biasQA[i] = baw[i - 256];
        return;
    }
    const int k = li / N, n = li % N;
    const float v = W[li];
    const __nv_bfloat16 h = __float2bfloat16(v);
    const __nv_bfloat16 l = __float2bfloat16(v - __bfloat162float(h));
    __nv_bfloat16* base = Bt + (size_t)(n + nofs) * KP2 + k;
    base[0]   = h;
    base[256] = l;
}

// ---------------------------------------------------------------------------
// GEMM core: BM=128, BN=128, BK=32, 8 warps (4x2), warp 32x64, 3-stage
// cp.async. nterms = 3: full compensation; nterms = 1: Ah*Bh only
// (skips lo cp.async, lo ldmatrix, and 2/3 of the mma).
// ---------------------------------------------------------------------------
__device__ __forceinline__ void gemm_body(
    const __nv_bfloat16* __restrict__ A, const __nv_bfloat16* __restrict__ Bt,
    const float* __restrict__ bias, const float* __restrict__ res,
    float* __restrict__ C, int M, int N, int m0, int n0, char* smem,
    int nterms)
{
    const uint32_t sBase = smem_u32(smem);
    const int tid  = threadIdx.x;
    const int lane = tid & 31;
    const int wid  = tid >> 5;
    const int wm   = wid & 3;
    const int wn   = wid >> 2;

    auto load_stage = [&](int stg, int kt) {
        const int kbase = kt * BK;
        const uint32_t sA = sBase + (uint32_t)stg * STAGE_B;
        const uint32_t sB = sA + TILE_E * 2;
#pragma unroll
        for (int it = 0; it < 4; it++) {
            const int c   = tid + it * 256;
            const int row = c >> 3;
            const int seg = (c & 7) << 3;
            if (nterms == 1 && seg >= 32) continue;   // skip lo halves
            const int gcol = (seg < 32) ? (kbase + seg) : (256 + kbase + seg - 32);
            const uint32_t soff = (uint32_t)(row * APAD2 + seg) * 2;
            const int ar = min(m0 + row, M - 1);
            cp_async16(sA + soff, A + (size_t)ar * KP2 + gcol);
            cp_async16(sB + soff, Bt + (size_t)(n0 + row) * KP2 + gcol);
        }
    };

    float acc[2][8][4];
#pragma unroll
    for (int mi = 0; mi < 2; mi++)
#pragma unroll
        for (int nj = 0; nj < 8; nj++)
#pragma unroll
            for (int k = 0; k < 4; k++) acc[mi][nj][k] = 0.f;

    load_stage(0, 0); cp_commit();
    load_stage(1, 1); cp_commit();

    int stg = 0;
#pragma unroll 1
    for (int kt = 0; kt < NKIT; kt++) {
        cp_wait<1>();
        __syncthreads();

        if (kt + 2 < NKIT) load_stage((stg + 2) % 3, kt + 2);
        cp_commit();   // empty groups at tail keep wait<1> exact

        const uint32_t aB = sBase + (uint32_t)stg * STAGE_B;
        const uint32_t bB = aB + TILE_E * 2;

#pragma unroll
        for (int ks = 0; ks < 2; ks++) {
            uint32_t ah[2][4], al[2][4];
#pragma unroll
            for (int mi = 0; mi < 2; mi++) {
                const int row = wm * 32 + mi * 16 + (lane & 15);
                const int col = ks * 16 + ((lane >> 4) << 3);
                ldmatrix_x4(ah[mi], aB + (uint32_t)(row * APAD2 + col) * 2);
                if (nterms == 3)
                    ldmatrix_x4(al[mi], aB + (uint32_t)(row * APAD2 + 32 + col) * 2);
            }
#pragma unroll
            for (int njp = 0; njp < 4; njp++) {
                const int row = wn * 64 + njp * 16 + ((lane >> 4) & 1) * 8 + (lane & 7);
                const int col = ks * 16 + ((lane >> 3) & 1) * 8;
                uint32_t bh[4], bl[4];
                ldmatrix_x4(bh, bB + (uint32_t)(row * APAD2 + col) * 2);
                if (nterms == 3)
                    ldmatrix_x4(bl, bB + (uint32_t)(row * APAD2 + 32 + col) * 2);
#pragma unroll
                for (int mi = 0; mi < 2; mi++) {
                    float* a0 = acc[mi][njp * 2];
                    float* a1 = acc[mi][njp * 2 + 1];
                    mma_bf16(a0, ah[mi], bh[0], bh[1]);
                    mma_bf16(a1, ah[mi], bh[2], bh[3]);
                    if (nterms == 3) {
                        mma_bf16(a0, ah[mi], bl[0], bl[1]);
                        mma_bf16(a1, ah[mi], bl[2], bl[3]);
                        mma_bf16(a0, al[mi], bh[0], bh[1]);
                        mma_bf16(a1, al[mi], bh[2], bh[3]);
                    }
                }
            }
        }
        stg = (stg + 1) % 3;
    }

#pragma unroll
    for (int mi = 0; mi < 2; mi++) {
#pragma unroll
        for (int nj = 0; nj < 8; nj++) {
            const int col = n0 + wn * 64 + nj * 8 + (lane & 3) * 2;
            const int r0  = m0 + wm * 32 + mi * 16 + (lane >> 2);
            const int r1  = r0 + 8;
            const float b0 = bias[col], b1 = bias[col + 1];
            if (r0 < M) {
                float2 o = make_float2(acc[mi][nj][0] + b0, acc[mi][nj][1] + b1);
                if (res) {
                    const float2 rv = *(const float2*)(res + (size_t)r0 * N + col);
                    o.x += rv.x; o.y += rv.y;
                }
                *(float2*)(C + (size_t)r0 * N + col) = o;
            }
            if (r1 < M) {
                float2 o = make_float2(acc[mi][nj][2] + b0, acc[mi][nj][3] + b1);
                if (res) {
                    const float2 rv = *(const float2*)(res + (size_t)r1 * N + col);
                    o.x += rv.x; o.y += rv.y;
                }
                *(float2*)(C + (size_t)r1 * N + col) = o;
            }
        }
    }
}

// Fused value+QA GEMM: y 0-1 -> value (3-term), y 2-4 -> QA (1-term).
__global__ __launch_bounds__(256, 2) void gemm_vqa(
    const __nv_bfloat16* __restrict__ Av, const __nv_bfloat16* __restrict__ Bv,
    const float* __restrict__ bv, float* __restrict__ Cv,
    const __nv_bfloat16* __restrict__ Aq, const __nv_bfloat16* __restrict__ Bqa,
    const float* __restrict__ bqa, float* __restrict__ Cqa, int M)
{
    extern __shared__ __align__(16) char smem[];
    const int y = blockIdx.y;
    const int m0 = blockIdx.x * 128;
    if (y < 2)
        gemm_body(Av, Bv, bv, nullptr, Cv, M, 256, m0, y * 128, smem, 3);
    else
        gemm_body(Aq, Bqa, bqa, nullptr, Cqa, M, QASTR, m0, (y - 2) * 128, smem, 1);
}

// Output GEMM (3-term, bias + residual epilogue).
__global__ __launch_bounds__(256, 2) void gemm_out(
    const __nv_bfloat16* __restrict__ A, const __nv_bfloat16* __restrict__ Bt,
    const float* __restrict__ bias, const float* __restrict__ res,
    float* __restrict__ C, int M)
{
    extern __shared__ __align__(16) char smem[];
    gemm_body(A, Bt, bias, res, C, M, 256, blockIdx.x * 128, blockIdx.y * 128,
              smem, 3);
}

// ---------------------------------------------------------------------------
// Sampler (round-6 float4 version — best measured). Block = 4 queries.
// ---------------------------------------------------------------------------
__global__ __launch_bounds__(256) void msda_sample4(
    const float* __restrict__ V, const float* __restrict__ QA,
    const float* __restrict__ refp,
    const int* __restrict__ shapes, const int* __restrict__ starts,
    __nv_bfloat16* __restrict__ outCat, int M)
{
    __shared__ int4   sOff[4][16][8];
    __shared__ float4 sW  [4][16][8];

    const int tid = threadIdx.x;

    // Phase A
    {
        const int wi  = tid << 1;
        const int bqL = wi >> 7;
        const int h   = (wi >> 4) & 7;
        const int pt0 = wi & 15;
        int bq = blockIdx.x * 4 + bqL;
        bq = min(bq, M - 1);

        const float2 lg = *(const float2*)(QA + (size_t)bq * QASTR + 256 + h * 16 + pt0);
        float mx = fmaxf(lg.x, lg.y);
#pragma unroll
        for (int off = 4; off; off >>= 1)
            mx = fmaxf(mx, __shfl_xor_sync(0xffffffffu, mx, off));
        const float e0 = expf(lg.x - mx);
        const float e1 = expf(lg.y - mx);
        float sm = e0 + e1;
#pragma unroll
        for (int off = 4; off; off >>= 1)
            sm += __shfl_xor_sync(0xffffffffu, sm, off);
        const float inv = 1.f / sm;

        const int l = pt0 >> 2;
        const int H = shapes[2 * l + 0];
        const int W = shapes[2 * l + 1];
        const int st = starts[l];
        const float2 rp = *(const float2*)(refp + ((size_t)bq * NLVL + l) * 2);
        const float4 so = *(const float4*)(QA + (size_t)bq * QASTR + h * 32 + pt0 * 2);

#pragma unroll
        for (int k = 0; k < 2; k++) {
            const int pt = pt0 + k;
            const float aw  = (k ? e1 : e0) * inv;
            const float sox = k ? so.z : so.x;
            const float soy = k ? so.w : so.y;

            const float x = fmaf(rp.x, (float)W, sox) - 0.5f;
            const float y = fmaf(rp.y, (float)H, soy) - 0.5f;
            const float xf = floorf(x), yf = floorf(y);
            const int x0 = (int)xf, y0 = (int)yf;
            const float wx1 = x - xf, wx0 = 1.f - wx1;
            const float wy1 = y - yf, wy0 = 1.f - wy1;

            const bool vx0 = (x0 >= 0) && (x0 < W);
            const bool vx1 = (x0 + 1 >= 0) && (x0 + 1 < W);
            const bool vy0 = (y0 >= 0) && (y0 < H);
            const bool vy1 = (y0 + 1 >= 0) && (y0 + 1 < H);

            const int cx0 = max(0, min(x0,     W - 1));
            const int cx1 = max(0, min(x0 + 1, W - 1));
            const int cy0 = max(0, min(y0,     H - 1));
            const int cy1 = max(0, min(y0 + 1, H - 1));

            int4 o;
            o.x = st + cy0 * W + cx0;
            o.y = st + cy0 * W + cx1;
            o.z = st + cy1 * W + cx0;
            o.w = st + cy1 * W + cx1;

            float4 w4;
            w4.x = (vx0 && vy0) ? wx0 * wy0 * aw : 0.f;
            w4.y = (vx1 && vy0) ? wx1 * wy0 * aw : 0.f;
            w4.z = (vx0 && vy1) ? wx0 * wy1 * aw : 0.f;
            w4.w = (vx1 && vy1) ? wx1 * wy1 * aw : 0.f;

            sOff[bqL][pt][h] = o;
            sW  [bqL][pt][h] = w4;
        }
    }
    __syncthreads();

    // Phase B
    const int warpId = tid >> 5;
    const int lane   = tid & 31;
    const int bqL    = warpId >> 1;
    const int h      = ((warpId & 1) << 2) + (lane >> 3);
    const int c4     = lane & 7;
    const int bq     = blockIdx.x * 4 + bqL;
    if (bq >= M) return;
    const int b = bq / NQ;

    const float* vb = V + (size_t)b * NQ * EDIM + h * 32 + c4 * 4;

    float4 acc = make_float4(0.f, 0.f, 0.f, 0.f);
#pragma unroll
    for (int pt = 0; pt < 16; pt++) {
        const int4   o = sOff[bqL][pt][h];
        const float4 w = sW  [bqL][pt][h];

        const float4 v0 = *(const float4*)(vb + (size_t)o.x * EDIM);
        const float4 v1 = *(const float4*)(vb + (size_t)o.y * EDIM);
        const float4 v2 = *(const float4*)(vb + (size_t)o.z * EDIM);
        const float4 v3 = *(const float4*)(vb + (size_t)o.w * EDIM);

        acc.x = fmaf(w.x, v0.x, acc.x); acc.y = fmaf(w.x, v0.y, acc.y);
        acc.z = fmaf(w.x, v0.z, acc.z); acc.w = fmaf(w.x, v0.w, acc.w);
        acc.x = fmaf(w.y, v1.x, acc.x); acc.y = fmaf(w.y, v1.y, acc.y);
        acc.z = fmaf(w.y, v1.z, acc.z); acc.w = fmaf(w.y, v1.w, acc.w);
        acc.x = fmaf(w.z, v2.x, acc.x); acc.y = fmaf(w.z, v2.y, acc.y);
        acc.z = fmaf(w.z, v2.z, acc.z); acc.w = fmaf(w.z, v2.w, acc.w);
        acc.x = fmaf(w.w, v3.x, acc.x); acc.y = fmaf(w.w, v3.y, acc.y);
        acc.z = fmaf(w.w, v3.z, acc.z); acc.w = fmaf(w.w, v3.w, acc.w);
    }

    __nv_bfloat16 hh[4], ll[4];
    const float f[4] = {acc.x, acc.y, acc.z, acc.w};
#pragma unroll
    for (int k = 0; k < 4; k++) {
        hh[k] = __float2bfloat16(f[k]);
        ll[k] = __float2bfloat16(f[k] - __bfloat162float(hh[k]));
    }
    __nv_bfloat16* base = outCat + (size_t)bq * KP2 + h * 32 + c4 * 4;
    *(uint2*)(base)       = *(const uint2*)hh;
    *(uint2*)(base + 256) = *(const uint2*)ll;
}

// ---------------------------------------------------------------------------
// Launch
// ---------------------------------------------------------------------------
extern "C" void kernel_launch(void* const* d_in, const int* in_sizes, int n_in,
                              void* d_out, int out_size)
{
    const float* query  = (const float*)d_in[0];
    const float* value  = (const float*)d_in[1];
    const float* refp   = (const float*)d_in[2];
    const int*   shapes = (const int*)  d_in[3];
    const int*   starts = (const int*)  d_in[4];
    const float* Wv  = (const float*)d_in[5];
    const float* bv  = (const float*)d_in[6];
    const float* Wso = (const float*)d_in[7];
    const float* bso = (const float*)d_in[8];
    const float* Waw = (const float*)d_in[9];
    const float* baw = (const float*)d_in[10];
    const float* Wo  = (const float*)d_in[11];
    const float* bo  = (const float*)d_in[12];
    float* out = (float*)d_out;

    const int M = in_sizes[0] / EDIM;   // 40394

    float *pV, *pQA, *pBiasQA;
    __nv_bfloat16 *pAval, *pAq, *pAtmp, *pBv, *pBqa, *pBo;
    cudaGetSymbolAddress((void**)&pV,     g_V);
    cudaGetSymbolAddress((void**)&pQA,    g_QA);
    cudaGetSymbolAddress((void**)&pBiasQA,g_biasQA);
    cudaGetSymbolAddress((void**)&pAval,  g_Aval);
    cudaGetSymbolAddress((void**)&pAq,    g_Aq);
    cudaGetSymbolAddress((void**)&pAtmp,  g_Atmp);
    cudaGetSymbolAddress((void**)&pBv,    g_Bv);
    cudaGetSymbolAddress((void**)&pBqa,   g_Bqa);
    cudaGetSymbolAddress((void**)&pBo,    g_Bo);

    cudaFuncSetAttribute(gemm_vqa, cudaFuncAttributeMaxDynamicSharedMemorySize, SMEM_GEMM);
    cudaFuncSetAttribute(gemm_out, cudaFuncAttributeMaxDynamicSharedMemorySize, SMEM_GEMM);

    const int n4 = M * (EDIM / 4);
    const int cvtB = (n4 + 255) / 256;
    const int wB   = (229760 + 255) / 256;
    const int mTiles = (M + 127) / 128;

    prep_all<<<2 * cvtB + wB, 256>>>(value, query, Wv, Wso, Waw, Wo, bso, baw,
                                     n4, cvtB);
    gemm_vqa<<<dim3(mTiles, 5), 256, SMEM_GEMM>>>(
        pAval, pBv, bv, pV, pAq, pBqa, pBiasQA, pQA, M);
    msda_sample4<<<(M + 3) / 4, 256>>>(pV, pQA, refp, shapes, starts, pAtmp, M);
    gemm_out<<<dim3(mTiles, 2), 256, SMEM_GEMM>>>(pAtmp, pBo, bo, query, out, M);
}